// round 3
// baseline (speedup 1.0000x reference)
#include <cuda_runtime.h>
#include <math.h>

#define BB 2
#define TT 2048
#define DDIM 2048
#define HH 16
#define HDIM 128
#define MR (BB * TT)        // 4096 rows
#define NQKV (3 * DDIM)     // 6144

// Scratch (device globals: allocation-free per harness rules)
__device__ float g_qkv[(size_t)MR * NQKV];   // [B*T, 3D]
__device__ float g_y[(size_t)MR * DDIM];     // [B*T, D]

// ---------------------------------------------------------------------------
// SGEMM: C[M,N] = A[M,K] @ B[K,N], all row-major, dims multiples of 128/16.
// 128x128 tile, BK=16, 256 threads, 8x8 per thread. ~70-80% of fp32 FFMA peak.
// ---------------------------------------------------------------------------
__device__ __forceinline__ void sgemm_body(const float* __restrict__ A,
                                           const float* __restrict__ B,
                                           float* __restrict__ C,
                                           int M, int N, int K)
{
    __shared__ float As[16][128];   // transposed: As[k][m]
    __shared__ float Bs[16][128];   // Bs[k][n]

    const int tid = threadIdx.x;
    const int tr = tid >> 4;             // 0..15 (row group)
    const int tc = tid & 15;             // 0..15 (col group)

    const int ar = tid >> 2;             // 0..63  (A load row)
    const int ac = (tid & 3) << 2;       // 0,4,8,12
    const int br = tid >> 5;             // 0..7   (B load row)
    const int bc = (tid & 31) << 2;      // 0..124

    const float* Ab = A + (size_t)(blockIdx.y * 128) * K;
    const float* Bb = B + blockIdx.x * 128;

    float acc[8][8];
#pragma unroll
    for (int i = 0; i < 8; i++)
#pragma unroll
        for (int j = 0; j < 8; j++) acc[i][j] = 0.f;

    for (int k0 = 0; k0 < K; k0 += 16) {
        // global loads issued before the sync: overlap with prior tile math
        float4 a0 = *(const float4*)(Ab + (size_t)ar        * K + k0 + ac);
        float4 a1 = *(const float4*)(Ab + (size_t)(ar + 64) * K + k0 + ac);
        float4 b0 = *(const float4*)(Bb + (size_t)(k0 + br)     * N + bc);
        float4 b1 = *(const float4*)(Bb + (size_t)(k0 + br + 8) * N + bc);
        __syncthreads();
        As[ac + 0][ar] = a0.x; As[ac + 1][ar] = a0.y;
        As[ac + 2][ar] = a0.z; As[ac + 3][ar] = a0.w;
        As[ac + 0][ar + 64] = a1.x; As[ac + 1][ar + 64] = a1.y;
        As[ac + 2][ar + 64] = a1.z; As[ac + 3][ar + 64] = a1.w;
        *(float4*)&Bs[br][bc]     = b0;
        *(float4*)&Bs[br + 8][bc] = b1;
        __syncthreads();

#pragma unroll
        for (int k = 0; k < 16; k++) {
            float a[8], b[8];
            *(float4*)(a)     = *(const float4*)&As[k][tr * 8];
            *(float4*)(a + 4) = *(const float4*)&As[k][tr * 8 + 4];
            *(float4*)(b)     = *(const float4*)&Bs[k][tc * 8];
            *(float4*)(b + 4) = *(const float4*)&Bs[k][tc * 8 + 4];
#pragma unroll
            for (int i = 0; i < 8; i++)
#pragma unroll
                for (int j = 0; j < 8; j++)
                    acc[i][j] = fmaf(a[i], b[j], acc[i][j]);
        }
    }

    float* Cb = C + (size_t)(blockIdx.y * 128 + tr * 8) * N + blockIdx.x * 128 + tc * 8;
#pragma unroll
    for (int i = 0; i < 8; i++) {
        *(float4*)(Cb + (size_t)i * N)     = make_float4(acc[i][0], acc[i][1], acc[i][2], acc[i][3]);
        *(float4*)(Cb + (size_t)i * N + 4) = make_float4(acc[i][4], acc[i][5], acc[i][6], acc[i][7]);
    }
}

__global__ void __launch_bounds__(256) qkv_gemm_kernel(const float* __restrict__ x,
                                                       const float* __restrict__ w)
{
    sgemm_body(x, w, g_qkv, MR, NQKV, DDIM);
}

__global__ void __launch_bounds__(256) proj_gemm_kernel(const float* __restrict__ w,
                                                        float* __restrict__ out)
{
    sgemm_body(g_y, w, out, MR, DDIM, DDIM);
}

// ---------------------------------------------------------------------------
// Flash attention (causal, fp32). One CTA = (q-tile of 64, head, batch).
// Br=Bc=64, HD=128. 256 threads as 16x16: thread (ty,tx) owns S rows 4ty..+3,
// S cols 4tx..+3, and O rows 4ty..+3 / cols 8tx..+7.
// K stored d-major in smem (Kts[d][token]) for conflict-free column reads.
// ---------------------------------------------------------------------------
#define LQ 132   // Q/V row stride (pad 4: keeps 16B alignment, breaks conflicts)
#define LK 68    // Kts row stride
#define LP 65    // P row stride
#define SMEM_FLASH ((64 * LQ + 128 * LK + 64 * LQ + 64 * LP) * sizeof(float))  // 119040 B

__global__ void __launch_bounds__(256) flash_kernel()
{
    extern __shared__ float sm[];
    float* Qs  = sm;                 // [64][LQ]
    float* Kts = Qs + 64 * LQ;       // [128][LK]  (Kts[d][token])
    float* Vs  = Kts + 128 * LK;     // [64][LQ]
    float* Ps  = Vs + 64 * LQ;       // [64][LP]

    const int qt = blockIdx.x;       // 0..31
    const int h  = blockIdx.y;       // 0..15
    const int b  = blockIdx.z;       // 0..1
    const int tid = threadIdx.x;
    const int ty = tid >> 4;
    const int tx = tid & 15;

    const int q0 = qt * 64;
    const float* base = g_qkv + (size_t)b * TT * NQKV + h * HDIM;

    // Load Q tile [64][128]
    {
        int r  = tid >> 2;
        int c0 = (tid & 3) * 32;
        const float* src = base + (size_t)(q0 + r) * NQKV + c0;
        float* dst = Qs + r * LQ + c0;
#pragma unroll
        for (int i = 0; i < 8; i++) ((float4*)dst)[i] = ((const float4*)src)[i];
    }

    float o[4][8];
#pragma unroll
    for (int i = 0; i < 4; i++)
#pragma unroll
        for (int c = 0; c < 8; c++) o[i][c] = 0.f;

    float m_i[4], l_i[4];
#pragma unroll
    for (int i = 0; i < 4; i++) { m_i[i] = -INFINITY; l_i[i] = 0.f; }

    const float scale = 0.088388347648318447f;  // 1/sqrt(128)

    for (int kt = 0; kt <= qt; kt++) {
        const int k0 = kt * 64;
        __syncthreads();  // protect K/V/P smem from previous iteration's readers
        // Load K (transposed to d-major) + V (row-major)
        {
            int r  = tid >> 2;
            int c0 = (tid & 3) * 32;
            const float* ks = base + (size_t)(k0 + r) * NQKV + DDIM + c0;
#pragma unroll
            for (int i = 0; i < 8; i++) {
                float4 v = ((const float4*)ks)[i];
                int c = c0 + i * 4;
                Kts[(c + 0) * LK + r] = v.x;
                Kts[(c + 1) * LK + r] = v.y;
                Kts[(c + 2) * LK + r] = v.z;
                Kts[(c + 3) * LK + r] = v.w;
            }
            const float* vs = base + (size_t)(k0 + r) * NQKV + 2 * DDIM + c0;
            float* vd = Vs + r * LQ + c0;
#pragma unroll
            for (int i = 0; i < 8; i++) ((float4*)vd)[i] = ((const float4*)vs)[i];
        }
        __syncthreads();

        // S[4][4] = Q Kt  (vectorized over d; Kts column reads conflict-free)
        float s[4][4];
#pragma unroll
        for (int i = 0; i < 4; i++)
#pragma unroll
            for (int j = 0; j < 4; j++) s[i][j] = 0.f;

#pragma unroll 8
        for (int d0 = 0; d0 < HDIM; d0 += 4) {
            float4 q[4];
#pragma unroll
            for (int i = 0; i < 4; i++)
                q[i] = *(const float4*)(Qs + (4 * ty + i) * LQ + d0);
#pragma unroll
            for (int dd = 0; dd < 4; dd++) {
                float4 kv = *(const float4*)(Kts + (d0 + dd) * LK + 4 * tx);
#pragma unroll
                for (int i = 0; i < 4; i++) {
                    float qd = ((const float*)&q[i])[dd];
                    s[i][0] = fmaf(qd, kv.x, s[i][0]);
                    s[i][1] = fmaf(qd, kv.y, s[i][1]);
                    s[i][2] = fmaf(qd, kv.z, s[i][2]);
                    s[i][3] = fmaf(qd, kv.w, s[i][3]);
                }
            }
        }

        // Scale + causal mask (only the diagonal tile needs masking)
        const bool diag = (kt == qt);
#pragma unroll
        for (int i = 0; i < 4; i++)
#pragma unroll
            for (int j = 0; j < 4; j++) {
                float v = s[i][j] * scale;
                if (diag && (4 * tx + j > 4 * ty + i)) v = -INFINITY;
                s[i][j] = v;
            }

        // Online softmax: per-row reduce across the 16 tx lanes (width-16 shfl)
        float rsum[4], alpha[4];
#pragma unroll
        for (int i = 0; i < 4; i++) {
            float v = fmaxf(fmaxf(s[i][0], s[i][1]), fmaxf(s[i][2], s[i][3]));
#pragma unroll
            for (int off = 8; off; off >>= 1)
                v = fmaxf(v, __shfl_xor_sync(0xffffffffu, v, off, 16));
            float mnew = fmaxf(m_i[i], v);
            alpha[i] = __expf(m_i[i] - mnew);
            m_i[i] = mnew;
            float rs = 0.f;
#pragma unroll
            for (int j = 0; j < 4; j++) {
                float p = __expf(s[i][j] - mnew);
                Ps[(4 * ty + i) * LP + 4 * tx + j] = p;
                rs += p;
            }
#pragma unroll
            for (int off = 8; off; off >>= 1)
                rs += __shfl_xor_sync(0xffffffffu, rs, off, 16);
            rsum[i] = rs;
        }
#pragma unroll
        for (int i = 0; i < 4; i++) {
            l_i[i] = l_i[i] * alpha[i] + rsum[i];
#pragma unroll
            for (int c = 0; c < 8; c++) o[i][c] *= alpha[i];
        }
        __syncthreads();  // Ps visible to all consumers

        // O += P V
#pragma unroll 8
        for (int j = 0; j < 64; j++) {
            float4 v0 = *(const float4*)(Vs + j * LQ + 8 * tx);
            float4 v1 = *(const float4*)(Vs + j * LQ + 8 * tx + 4);
#pragma unroll
            for (int i = 0; i < 4; i++) {
                float p = Ps[(4 * ty + i) * LP + j];
                o[i][0] = fmaf(p, v0.x, o[i][0]);
                o[i][1] = fmaf(p, v0.y, o[i][1]);
                o[i][2] = fmaf(p, v0.z, o[i][2]);
                o[i][3] = fmaf(p, v0.w, o[i][3]);
                o[i][4] = fmaf(p, v1.x, o[i][4]);
                o[i][5] = fmaf(p, v1.y, o[i][5]);
                o[i][6] = fmaf(p, v1.z, o[i][6]);
                o[i][7] = fmaf(p, v1.w, o[i][7]);
            }
        }
    }

    // Epilogue: y[b, t, h*HD + c] = o / l  (head-interleaved layout == concat heads)
#pragma unroll
    for (int i = 0; i < 4; i++) {
        float inv = 1.f / l_i[i];
        int row = q0 + 4 * ty + i;
        float* dst = g_y + (size_t)(b * TT + row) * DDIM + h * HDIM + 8 * tx;
        *(float4*)dst       = make_float4(o[i][0] * inv, o[i][1] * inv, o[i][2] * inv, o[i][3] * inv);
        *(float4*)(dst + 4) = make_float4(o[i][4] * inv, o[i][5] * inv, o[i][6] * inv, o[i][7] * inv);
    }
}

// ---------------------------------------------------------------------------
extern "C" void kernel_launch(void* const* d_in, const int* in_sizes, int n_in,
                              void* d_out, int out_size)
{
    (void)in_sizes; (void)n_in; (void)out_size;
    const float* x      = (const float*)d_in[0];
    const float* w_attn = (const float*)d_in[1];
    const float* w_proj = (const float*)d_in[2];
    float* out = (float*)d_out;

    // Host-side attribute set: immediate (not stream-ordered), capture-safe.
    cudaFuncSetAttribute(flash_kernel, cudaFuncAttributeMaxDynamicSharedMemorySize,
                         (int)SMEM_FLASH);

    dim3 g1(NQKV / 128, MR / 128);   // (48, 32)
    qkv_gemm_kernel<<<g1, 256>>>(x, w_attn);

    dim3 g2(TT / 64, HH, BB);        // (32, 16, 2)
    flash_kernel<<<g2, 256, SMEM_FLASH>>>();

    dim3 g3(DDIM / 128, MR / 128);   // (16, 32)
    proj_gemm_kernel<<<g3, 256>>>(w_proj, out);
}

// round 8
// speedup vs baseline: 1.7993x; 1.7993x over previous
#include <cuda_runtime.h>
#include <cuda_bf16.h>
#include <math.h>
#include <stdint.h>

#define BB 2
#define TT 2048
#define DDIM 2048
#define HH 16
#define HDIM 128
#define MR (BB * TT)        // 4096
#define NQKV (3 * DDIM)     // 6144

// ---------------- scratch (device globals: allocation-free) ----------------
__device__ float g_qkv[(size_t)MR * NQKV];     // [B*T, 3D] fp32
__device__ float g_y[(size_t)MR * DDIM];       // [B*T, D] fp32
__device__ __nv_bfloat16 g_xh[(size_t)MR * DDIM],   g_xl[(size_t)MR * DDIM];
__device__ __nv_bfloat16 g_wah[(size_t)NQKV * DDIM], g_wal[(size_t)NQKV * DDIM]; // [N,K]
__device__ __nv_bfloat16 g_wph[(size_t)DDIM * DDIM], g_wpl[(size_t)DDIM * DDIM]; // [N,K]
__device__ __nv_bfloat16 g_yh[(size_t)MR * DDIM],   g_yl[(size_t)MR * DDIM];

// ---------------- helpers ----------------
__device__ __forceinline__ uint32_t smem_u32(const void* p) {
    uint32_t a;
    asm("{ .reg .u64 t; cvta.to.shared.u64 t, %1; cvt.u32.u64 %0, t; }" : "=r"(a) : "l"(p));
    return a;
}
__device__ __forceinline__ void cp16(uint32_t dst, const void* src) {
    asm volatile("cp.async.cg.shared.global [%0], [%1], 16;\n" :: "r"(dst), "l"(src) : "memory");
}
__device__ __forceinline__ void cp_commit() { asm volatile("cp.async.commit_group;\n" ::: "memory"); }
__device__ __forceinline__ void cp_wait1()  { asm volatile("cp.async.wait_group 1;\n" ::: "memory"); }
__device__ __forceinline__ void cp_wait0()  { asm volatile("cp.async.wait_group 0;\n" ::: "memory"); }

__device__ __forceinline__ void ldsm4(uint32_t* r, uint32_t addr) {
    asm volatile("ldmatrix.sync.aligned.m8n8.x4.shared.b16 {%0,%1,%2,%3}, [%4];"
                 : "=r"(r[0]), "=r"(r[1]), "=r"(r[2]), "=r"(r[3]) : "r"(addr));
}
__device__ __forceinline__ void mma16816(float* c, const uint32_t* a, const uint32_t* b) {
    asm volatile(
        "mma.sync.aligned.m16n8k16.row.col.f32.bf16.bf16.f32 "
        "{%0,%1,%2,%3}, {%4,%5,%6,%7}, {%8,%9}, {%0,%1,%2,%3};"
        : "+f"(c[0]), "+f"(c[1]), "+f"(c[2]), "+f"(c[3])
        : "r"(a[0]), "r"(a[1]), "r"(a[2]), "r"(a[3]), "r"(b[0]), "r"(b[1]));
}

// ---------------- bf16 split conversion kernels ----------------
__device__ __forceinline__ uint32_t pack2(__nv_bfloat16 a, __nv_bfloat16 b) {
    __nv_bfloat162 t; t.x = a; t.y = b;
    return *(uint32_t*)&t;
}

__device__ __forceinline__ void split_body(const float* __restrict__ src,
                                           __nv_bfloat16* __restrict__ hi,
                                           __nv_bfloat16* __restrict__ lo) {
    size_t i = (size_t)blockIdx.x * blockDim.x + threadIdx.x;  // one float4
    float4 v = ((const float4*)src)[i];
    float f[4] = {v.x, v.y, v.z, v.w};
    __nv_bfloat16 h[4], l[4];
#pragma unroll
    for (int j = 0; j < 4; j++) {
        h[j] = __float2bfloat16(f[j]);
        l[j] = __float2bfloat16(f[j] - __bfloat162float(h[j]));
    }
    ((uint2*)hi)[i] = make_uint2(pack2(h[0], h[1]), pack2(h[2], h[3]));
    ((uint2*)lo)[i] = make_uint2(pack2(l[0], l[1]), pack2(l[2], l[3]));
}

__global__ void __launch_bounds__(256) split_x_kernel(const float* __restrict__ x) {
    split_body(x, g_xh, g_xl);
}
__global__ void __launch_bounds__(256) split_y_kernel() {
    split_body(g_y, g_yh, g_yl);
}

// src [K,N] row-major fp32 -> hi/lo [N,K] bf16 (transposed split)
__device__ __forceinline__ void splitT_body(const float* __restrict__ src,
                                            __nv_bfloat16* __restrict__ hi,
                                            __nv_bfloat16* __restrict__ lo,
                                            int K, int N) {
    __shared__ float t[32][33];
    int tx = threadIdx.x, ty = threadIdx.y;
    int n0 = blockIdx.x * 32, k0 = blockIdx.y * 32;
#pragma unroll
    for (int i = 0; i < 4; i++)
        t[ty + i * 8][tx] = src[(size_t)(k0 + ty + i * 8) * N + n0 + tx];
    __syncthreads();
#pragma unroll
    for (int i = 0; i < 4; i++) {
        float v = t[tx][ty + i * 8];
        __nv_bfloat16 h = __float2bfloat16(v);
        __nv_bfloat16 l = __float2bfloat16(v - __bfloat162float(h));
        size_t o = (size_t)(n0 + ty + i * 8) * K + k0 + tx;
        hi[o] = h; lo[o] = l;
    }
}

__global__ void split_wa_kernel(const float* __restrict__ w) { splitT_body(w, g_wah, g_wal, DDIM, NQKV); }
__global__ void split_wp_kernel(const float* __restrict__ w) { splitT_body(w, g_wph, g_wpl, DDIM, DDIM); }

// ---------------- mma.sync bf16-split GEMM ----------------
// C[M,N] = A[M,K] * B[N,K]^T (both K-major), fp32 out.
// CTA tile 128x128, BK=32, 256 threads = 8 warps (4 m x 2 n), warp tile 32x64.
// smem tiles: 128 rows x 32 bf16 (64B/row), 16B chunks XOR-swizzled by (row>>1)&3.
#define TSZ 8192                        // one tile: 128 * 64 B
#define STAGE_SZ (4 * TSZ)              // Ah, Al, Bh, Bl
#define SMEM_MMA (2 * STAGE_SZ)         // 65536 B double-buffered

__device__ __forceinline__ uint32_t tile_off(int r, int cbyte) {
    return (uint32_t)(r * 64 + ((((cbyte >> 4) ^ ((r >> 1) & 3)) << 4)));
}

__device__ __forceinline__ void load_stage_mma(uint32_t base,
    const __nv_bfloat16* __restrict__ Ah, const __nv_bfloat16* __restrict__ Al,
    const __nv_bfloat16* __restrict__ Bh, const __nv_bfloat16* __restrict__ Bl,
    int m0, int n0, int k0, int K, int tid)
{
#pragma unroll
    for (int half = 0; half < 2; half++) {
        int idx = half * 256 + tid;        // 0..511
        int r = idx >> 2, c = (idx & 3);
        uint32_t o = tile_off(r, c * 16);
        const size_t ao = (size_t)(m0 + r) * K + k0 + c * 8;
        const size_t bo = (size_t)(n0 + r) * K + k0 + c * 8;
        cp16(base + o,           Ah + ao);
        cp16(base + TSZ + o,     Al + ao);
        cp16(base + 2 * TSZ + o, Bh + bo);
        cp16(base + 3 * TSZ + o, Bl + bo);
    }
}

__device__ void gemm_mma_body(const __nv_bfloat16* __restrict__ Ah, const __nv_bfloat16* __restrict__ Al,
                              const __nv_bfloat16* __restrict__ Bh, const __nv_bfloat16* __restrict__ Bl,
                              float* __restrict__ C, int M, int N, int K)
{
    extern __shared__ char smem[];
    const uint32_t sb = smem_u32(smem);
    const int tid  = threadIdx.x;
    const int lane = tid & 31;
    const int wid  = tid >> 5;
    const int wm   = wid & 3;        // 0..3 -> m block of 32
    const int wn   = wid >> 2;       // 0..1 -> n block of 64
    const int m0 = blockIdx.y * 128;
    const int n0 = blockIdx.x * 128;

    float acc[2][8][4];
#pragma unroll
    for (int i = 0; i < 2; i++)
#pragma unroll
        for (int j = 0; j < 8; j++)
#pragma unroll
            for (int q = 0; q < 4; q++) acc[i][j][q] = 0.f;

    // per-lane ldmatrix row/byte layout (canonical m16n8k16 frag mappings)
    const int a_r  = (lane & 7) + ((lane >> 3) & 1) * 8;   // row within m16
    const int a_kb = (lane >> 4) * 16;                     // byte within k16 slice
    const int b_r  = (lane & 7) + ((lane >> 4) << 3);      // row within n16 group
    const int b_kb = ((lane >> 3) & 1) * 16;

    const int NIT = K / 32;          // 64
    load_stage_mma(sb,            Ah, Al, Bh, Bl, m0, n0, 0,  K, tid); cp_commit();
    load_stage_mma(sb + STAGE_SZ, Ah, Al, Bh, Bl, m0, n0, 32, K, tid); cp_commit();

    for (int it = 0; it < NIT; ++it) {
        if (it + 1 < NIT) cp_wait1(); else cp_wait0();
        __syncthreads();
        const uint32_t st = sb + (uint32_t)(it & 1) * STAGE_SZ;

#pragma unroll
        for (int k16 = 0; k16 < 2; k16++) {
#pragma unroll
            for (int p = 0; p < 3; p++) {   // Ah*Bh, Ah*Bl, Al*Bh
                const uint32_t at = st + ((p == 2) ? TSZ : 0);
                const uint32_t bt = st + 2 * TSZ + ((p == 1) ? TSZ : 0);
                uint32_t a[2][4];
#pragma unroll
                for (int mf = 0; mf < 2; mf++) {
                    int r = wm * 32 + mf * 16 + a_r;
                    ldsm4(a[mf], at + tile_off(r, k16 * 32 + a_kb));
                }
                uint32_t b[8][2];
#pragma unroll
                for (int g = 0; g < 4; g++) {
                    int r = wn * 64 + g * 16 + b_r;
                    uint32_t t[4];
                    ldsm4(t, bt + tile_off(r, k16 * 32 + b_kb));
                    b[2 * g][0] = t[0]; b[2 * g][1] = t[1];
                    b[2 * g + 1][0] = t[2]; b[2 * g + 1][1] = t[3];
                }
#pragma unroll
                for (int mf = 0; mf < 2; mf++)
#pragma unroll
                    for (int nf = 0; nf < 8; nf++)
                        mma16816(acc[mf][nf], a[mf], b[nf]);
            }
        }
        __syncthreads();
        if (it + 2 < NIT) {
            load_stage_mma(st, Ah, Al, Bh, Bl, m0, n0, (it + 2) * 32, K, tid);
            cp_commit();
        }
    }

    // epilogue: c frag layout -> (row = base + lane>>2 [+8], col = base + (lane&3)*2)
    const int rr = lane >> 2;
    const int cc = (lane & 3) * 2;
#pragma unroll
    for (int mf = 0; mf < 2; mf++) {
        const int row = m0 + wm * 32 + mf * 16 + rr;
#pragma unroll
        for (int nf = 0; nf < 8; nf++) {
            const int col = n0 + wn * 64 + nf * 8 + cc;
            *(float2*)(C + (size_t)row * N + col)       = make_float2(acc[mf][nf][0], acc[mf][nf][1]);
            *(float2*)(C + (size_t)(row + 8) * N + col) = make_float2(acc[mf][nf][2], acc[mf][nf][3]);
        }
    }
}

__global__ void __launch_bounds__(256, 2) qkv_gemm_kernel() {
    gemm_mma_body(g_xh, g_xl, g_wah, g_wal, g_qkv, MR, NQKV, DDIM);
}
__global__ void __launch_bounds__(256, 2) proj_gemm_kernel(float* __restrict__ out) {
    gemm_mma_body(g_yh, g_yl, g_wph, g_wpl, out, MR, DDIM, DDIM);
}

// ---------------------------------------------------------------------------
// Flash attention (causal, fp32) — unchanged from the passing round-2 kernel
// ---------------------------------------------------------------------------
#define LQ 132
#define LK 68
#define LP 65
#define SMEM_FLASH ((64 * LQ + 128 * LK + 64 * LQ + 64 * LP) * sizeof(float))

__global__ void __launch_bounds__(256) flash_kernel()
{
    extern __shared__ float sm[];
    float* Qs  = sm;
    float* Kts = Qs + 64 * LQ;
    float* Vs  = Kts + 128 * LK;
    float* Ps  = Vs + 64 * LQ;

    const int qt = blockIdx.x;
    const int h  = blockIdx.y;
    const int b  = blockIdx.z;
    const int tid = threadIdx.x;
    const int ty = tid >> 4;
    const int tx = tid & 15;

    const int q0 = qt * 64;
    const float* base = g_qkv + (size_t)b * TT * NQKV + h * HDIM;

    {
        int r  = tid >> 2;
        int c0 = (tid & 3) * 32;
        const float* src = base + (size_t)(q0 + r) * NQKV + c0;
        float* dst = Qs + r * LQ + c0;
#pragma unroll
        for (int i = 0; i < 8; i++) ((float4*)dst)[i] = ((const float4*)src)[i];
    }

    float o[4][8];
#pragma unroll
    for (int i = 0; i < 4; i++)
#pragma unroll
        for (int c = 0; c < 8; c++) o[i][c] = 0.f;

    float m_i[4], l_i[4];
#pragma unroll
    for (int i = 0; i < 4; i++) { m_i[i] = -INFINITY; l_i[i] = 0.f; }

    const float scale = 0.088388347648318447f;

    for (int kt = 0; kt <= qt; kt++) {
        const int k0 = kt * 64;
        __syncthreads();
        {
            int r  = tid >> 2;
            int c0 = (tid & 3) * 32;
            const float* ks = base + (size_t)(k0 + r) * NQKV + DDIM + c0;
#pragma unroll
            for (int i = 0; i < 8; i++) {
                float4 v = ((const float4*)ks)[i];
                int c = c0 + i * 4;
                Kts[(c + 0) * LK + r] = v.x;
                Kts[(c + 1) * LK + r] = v.y;
                Kts[(c + 2) * LK + r] = v.z;
                Kts[(c + 3) * LK + r] = v.w;
            }
            const float* vs = base + (size_t)(k0 + r) * NQKV + 2 * DDIM + c0;
            float* vd = Vs + r * LQ + c0;
#pragma unroll
            for (int i = 0; i < 8; i++) ((float4*)vd)[i] = ((const float4*)vs)[i];
        }
        __syncthreads();

        float s[4][4];
#pragma unroll
        for (int i = 0; i < 4; i++)
#pragma unroll
            for (int j = 0; j < 4; j++) s[i][j] = 0.f;

#pragma unroll 8
        for (int d0 = 0; d0 < HDIM; d0 += 4) {
            float4 q[4];
#pragma unroll
            for (int i = 0; i < 4; i++)
                q[i] = *(const float4*)(Qs + (4 * ty + i) * LQ + d0);
#pragma unroll
            for (int dd = 0; dd < 4; dd++) {
                float4 kv = *(const float4*)(Kts + (d0 + dd) * LK + 4 * tx);
#pragma unroll
                for (int i = 0; i < 4; i++) {
                    float qd = ((const float*)&q[i])[dd];
                    s[i][0] = fmaf(qd, kv.x, s[i][0]);
                    s[i][1] = fmaf(qd, kv.y, s[i][1]);
                    s[i][2] = fmaf(qd, kv.z, s[i][2]);
                    s[i][3] = fmaf(qd, kv.w, s[i][3]);
                }
            }
        }

        const bool diag = (kt == qt);
#pragma unroll
        for (int i = 0; i < 4; i++)
#pragma unroll
            for (int j = 0; j < 4; j++) {
                float v = s[i][j] * scale;
                if (diag && (4 * tx + j > 4 * ty + i)) v = -INFINITY;
                s[i][j] = v;
            }

        float rsum[4], alpha[4];
#pragma unroll
        for (int i = 0; i < 4; i++) {
            float v = fmaxf(fmaxf(s[i][0], s[i][1]), fmaxf(s[i][2], s[i][3]));
#pragma unroll
            for (int off = 8; off; off >>= 1)
                v = fmaxf(v, __shfl_xor_sync(0xffffffffu, v, off, 16));
            float mnew = fmaxf(m_i[i], v);
            alpha[i] = __expf(m_i[i] - mnew);
            m_i[i] = mnew;
            float rs = 0.f;
#pragma unroll
            for (int j = 0; j < 4; j++) {
                float p = __expf(s[i][j] - mnew);
                Ps[(4 * ty + i) * LP + 4 * tx + j] = p;
                rs += p;
            }
#pragma unroll
            for (int off = 8; off; off >>= 1)
                rs += __shfl_xor_sync(0xffffffffu, rs, off, 16);
            rsum[i] = rs;
        }
#pragma unroll
        for (int i = 0; i < 4; i++) {
            l_i[i] = l_i[i] * alpha[i] + rsum[i];
#pragma unroll
            for (int c = 0; c < 8; c++) o[i][c] *= alpha[i];
        }
        __syncthreads();

#pragma unroll 8
        for (int j = 0; j < 64; j++) {
            float4 v0 = *(const float4*)(Vs + j * LQ + 8 * tx);
            float4 v1 = *(const float4*)(Vs + j * LQ + 8 * tx + 4);
#pragma unroll
            for (int i = 0; i < 4; i++) {
                float p = Ps[(4 * ty + i) * LP + j];
                o[i][0] = fmaf(p, v0.x, o[i][0]);
                o[i][1] = fmaf(p, v0.y, o[i][1]);
                o[i][2] = fmaf(p, v0.z, o[i][2]);
                o[i][3] = fmaf(p, v0.w, o[i][3]);
                o[i][4] = fmaf(p, v1.x, o[i][4]);
                o[i][5] = fmaf(p, v1.y, o[i][5]);
                o[i][6] = fmaf(p, v1.z, o[i][6]);
                o[i][7] = fmaf(p, v1.w, o[i][7]);
            }
        }
    }

#pragma unroll
    for (int i = 0; i < 4; i++) {
        float inv = 1.f / l_i[i];
        int row = q0 + 4 * ty + i;
        float* dst = g_y + (size_t)(b * TT + row) * DDIM + h * HDIM + 8 * tx;
        *(float4*)dst       = make_float4(o[i][0] * inv, o[i][1] * inv, o[i][2] * inv, o[i][3] * inv);
        *(float4*)(dst + 4) = make_float4(o[i][4] * inv, o[i][5] * inv, o[i][6] * inv, o[i][7] * inv);
    }
}

// ---------------------------------------------------------------------------
extern "C" void kernel_launch(void* const* d_in, const int* in_sizes, int n_in,
                              void* d_out, int out_size)
{
    (void)in_sizes; (void)n_in; (void)out_size;
    const float* x      = (const float*)d_in[0];
    const float* w_attn = (const float*)d_in[1];
    const float* w_proj = (const float*)d_in[2];
    float* out = (float*)d_out;

    cudaFuncSetAttribute(flash_kernel,     cudaFuncAttributeMaxDynamicSharedMemorySize, (int)SMEM_FLASH);
    cudaFuncSetAttribute(qkv_gemm_kernel,  cudaFuncAttributeMaxDynamicSharedMemorySize, SMEM_MMA);
    cudaFuncSetAttribute(proj_gemm_kernel, cudaFuncAttributeMaxDynamicSharedMemorySize, SMEM_MMA);

    // bf16 hi/lo splits (+ weight transposes to [N,K])
    split_x_kernel<<<(size_t)MR * DDIM / 4 / 256, 256>>>(x);
    split_wa_kernel<<<dim3(NQKV / 32, DDIM / 32), dim3(32, 8)>>>(w_attn);
    split_wp_kernel<<<dim3(DDIM / 32, DDIM / 32), dim3(32, 8)>>>(w_proj);

    // qkv = x @ w_attn
    qkv_gemm_kernel<<<dim3(NQKV / 128, MR / 128), 256, SMEM_MMA>>>();

    flash_kernel<<<dim3(TT / 64, HH, BB), 256, SMEM_FLASH>>>();

    split_y_kernel<<<(size_t)MR * DDIM / 4 / 256, 256>>>();

    // out = y @ w_proj
    proj_gemm_kernel<<<dim3(DDIM / 128, MR / 128), 256, SMEM_MMA>>>(out);
}